// round 3
// baseline (speedup 1.0000x reference)
#include <cuda_runtime.h>
#include <cstdint>

#define Bc 2
#define Hc 16
#define Sc 2048
#define Dc 64
#define NROWS (Bc * Hc * Sc)   // 65536
#define SP1 (Sc + 1)           // 2049
#define NTILES 528             // 32*33/2 causal (qt,kt) tile pairs at 64x64

// Scratch (allocation-free): per-row log2e/||k|| and softmax partial sums.
__device__ float g_invn[NROWS];
__device__ float g_rowsum[NROWS];

// ---------------------------------------------------------------------------
// Kernel 1: per-key log2(e)/||k|| + zero row sums. Folding log2e here puts
// scores directly in the log2 domain -> exp = bare EX2 / bare 2^f poly.
// ---------------------------------------------------------------------------
__global__ __launch_bounds__(256) void prep_kernel(const float* __restrict__ k) {
    int row = blockIdx.x * blockDim.x + threadIdx.x;
    if (row >= NROWS) return;
    const float4* kr = (const float4*)(k + (size_t)row * Dc);
    float s = 0.f;
#pragma unroll
    for (int i = 0; i < Dc / 4; i++) {
        float4 v = kr[i];
        s += v.x * v.x + v.y * v.y + v.z * v.z + v.w * v.w;
    }
    g_invn[row] = 1.4426950408889634f * rsqrtf(s);
    g_rowsum[row] = 0.f;
}

// ---------------------------------------------------------------------------
// Packed fp32x2 helpers (Blackwell): ptxas will not auto-fuse; must be PTX.
// ---------------------------------------------------------------------------
__device__ __forceinline__ unsigned long long ffma2(unsigned long long a,
                                                    unsigned long long b,
                                                    unsigned long long c) {
    unsigned long long d;
    asm("fma.rn.f32x2 %0, %1, %2, %3;" : "=l"(d) : "l"(a), "l"(b), "l"(c));
    return d;
}
__device__ __forceinline__ unsigned long long fadd2(unsigned long long a,
                                                    unsigned long long b) {
    unsigned long long d;
    asm("add.rn.f32x2 %0, %1, %2;" : "=l"(d) : "l"(a), "l"(b));
    return d;
}
__device__ __forceinline__ unsigned long long fmul2(unsigned long long a,
                                                    unsigned long long b) {
    unsigned long long d;
    asm("mul.rn.f32x2 %0, %1, %2;" : "=l"(d) : "l"(a), "l"(b));
    return d;
}
__device__ __forceinline__ unsigned long long pack2(float x, float y) {
    union { float2 f; unsigned long long u; } cv;
    cv.f = make_float2(x, y);
    return cv.u;
}
__device__ __forceinline__ float2 unpack2(unsigned long long u) {
    union { float2 f; unsigned long long u; } cv;
    cv.u = u;
    return cv.f;
}
__device__ __forceinline__ float ex2_mufu(float x) {   // single MUFU.EX2
    float r;
    asm("ex2.approx.f32 %0, %1;" : "=f"(r) : "f"(x));
    return r;
}

// Packed 2^x for a pair of values, |x| <= ~20. Range-reduce via the
// magic-number round; exponent insertion on the ALU pipe (SHF+IADD), keeping
// the fma pipe free for the poly. Degree-5 Taylor on [-0.5,0.5]: ~3e-6 rel.
__device__ __forceinline__ unsigned long long exp2_poly2(unsigned long long u) {
    const unsigned long long MAGIC  = pack2(12582912.f, 12582912.f);   // 1.5*2^23
    const unsigned long long NMAGIC = pack2(-12582912.f, -12582912.f);
    const unsigned long long NONE   = pack2(-1.f, -1.f);
    const unsigned long long C5 = pack2(1.3333558e-3f, 1.3333558e-3f);
    const unsigned long long C4 = pack2(9.6181291e-3f, 9.6181291e-3f);
    const unsigned long long C3 = pack2(5.5504109e-2f, 5.5504109e-2f);
    const unsigned long long C2 = pack2(2.4022651e-1f, 2.4022651e-1f);
    const unsigned long long C1 = pack2(6.9314718e-1f, 6.9314718e-1f);
    const unsigned long long C0 = pack2(1.f, 1.f);

    unsigned long long r2 = fadd2(u, MAGIC);     // round(x) in low mantissa
    unsigned long long e2 = fadd2(r2, NMAGIC);   // float(round(x))
    unsigned long long f2 = ffma2(e2, NONE, u);  // frac = x - round(x)
    unsigned long long p  = ffma2(C5, f2, C4);
    p = ffma2(p, f2, C3);
    p = ffma2(p, f2, C2);
    p = ffma2(p, f2, C1);
    p = ffma2(p, f2, C0);
    unsigned int rlo, rhi;
    asm("mov.b64 {%0,%1}, %2;" : "=r"(rlo), "=r"(rhi) : "l"(r2));
    unsigned int slo = (rlo << 23) + 0x3F800000u;   // 2^i bits (alu pipe)
    unsigned int shi = (rhi << 23) + 0x3F800000u;
    unsigned long long s2;
    asm("mov.b64 %0, {%1,%2};" : "=l"(s2) : "r"(slo), "r"(shi));
    return fmul2(p, s2);
}

// ---------------------------------------------------------------------------
// Kernel 2: ONE 64x64 causal tile per CTA. FFMA2 GEMM; epilogue splits the
// 16 exps per thread 10:6 between MUFU.EX2 and the packed fma-pipe poly so
// both pipes run concurrently (MUFU alone is the round-2 bottleneck).
// ---------------------------------------------------------------------------
__global__ __launch_bounds__(256) void scores_kernel(const float* __restrict__ q,
                                                     const float* __restrict__ k,
                                                     float* __restrict__ out) {
    __shared__ unsigned long long sq[32 * 64];  // [d2][qrow]
    __shared__ unsigned long long sk[32 * 64];  // [d2][key], pre-scaled

    const int p = blockIdx.x;
    int qt = (int)((sqrtf(8.0f * (float)p + 1.0f) - 1.0f) * 0.5f);
    while ((qt + 1) * (qt + 2) / 2 <= p) qt++;
    while (qt * (qt + 1) / 2 > p) qt--;
    const int kt = p - qt * (qt + 1) / 2;

    const int bh = blockIdx.y;
    const int t  = threadIdx.x;
    const int i0 = qt * 64;
    const int j0 = kt * 64;
    const size_t base = (size_t)bh * Sc;

    {
        const float4* qg = (const float4*)(q + (base + i0) * Dc);
        const float4* kg = (const float4*)(k + (base + j0) * Dc);
#pragma unroll
        for (int it = 0; it < 4; it++) {
            int idx = t + 256 * it;
            int row = idx >> 4, c4 = idx & 15;
            float4 v = qg[row * 16 + c4];
            sq[(2 * c4) * 64 + row]     = pack2(v.x, v.y);
            sq[(2 * c4 + 1) * 64 + row] = pack2(v.z, v.w);
            float s = g_invn[base + j0 + row];
            float4 u = kg[row * 16 + c4];
            sk[(2 * c4) * 64 + row]     = pack2(u.x * s, u.y * s);
            sk[(2 * c4 + 1) * 64 + row] = pack2(u.z * s, u.w * s);
        }
    }
    __syncthreads();

    const int tx = t & 15;
    const int ty = t >> 4;

    unsigned long long acc[4][4];
#pragma unroll
    for (int r = 0; r < 4; r++)
#pragma unroll
        for (int c = 0; c < 4; c++) acc[r][c] = 0ull;

#pragma unroll 8
    for (int d2 = 0; d2 < 32; d2++) {
        unsigned long long qv[4], kv[4];
#pragma unroll
        for (int r = 0; r < 4; r++) qv[r] = sq[d2 * 64 + ty + 16 * r];
#pragma unroll
        for (int c = 0; c < 4; c++) kv[c] = sk[d2 * 64 + tx + 16 * c];
#pragma unroll
        for (int r = 0; r < 4; r++)
#pragma unroll
            for (int c = 0; c < 4; c++)
                acc[r][c] = ffma2(qv[r], kv[c], acc[r][c]);
    }

    // w[r][c] in log2 domain
    float w[4][4];
#pragma unroll
    for (int r = 0; r < 4; r++)
#pragma unroll
        for (int c = 0; c < 4; c++) {
            float2 f = unpack2(acc[r][c]);
            w[r][c] = f.x + f.y;
        }

    // exp split: MUFU for c=0,1 (all r) + r=3 c=2,3  (10 values);
    // packed poly for r=0..2, c=2,3 (3 pairs = 6 values).
    float ew[4][4];
#pragma unroll
    for (int r = 0; r < 4; r++) {
        ew[r][0] = ex2_mufu(w[r][0]);
        ew[r][1] = ex2_mufu(w[r][1]);
    }
    ew[3][2] = ex2_mufu(w[3][2]);
    ew[3][3] = ex2_mufu(w[3][3]);
#pragma unroll
    for (int r = 0; r < 3; r++) {
        float2 e = unpack2(exp2_poly2(pack2(w[r][2], w[r][3])));
        ew[r][2] = e.x;
        ew[r][3] = e.y;
    }

    const bool diag = (kt == qt);
#pragma unroll
    for (int r = 0; r < 4; r++) {
        const int i = i0 + ty + 16 * r;
        const size_t orow = (base + (size_t)i) * SP1;
        float psum = 0.f;
#pragma unroll
        for (int c = 0; c < 4; c++) {
            const int j = j0 + tx + 16 * c;
            if (!diag || j <= i) {
                out[orow + j] = ew[r][c];
                psum += ew[r][c];
            }
        }
#pragma unroll
        for (int m = 8; m >= 1; m >>= 1)
            psum += __shfl_xor_sync(0xffffffffu, psum, m);
        if (tx == 0) atomicAdd(&g_rowsum[base + i], psum);  // REDG
    }
}

// ---------------------------------------------------------------------------
// Kernel 3: normalize. Z = sum_{j<=i} exp(w) + (S-1-i) + exp(sink).
// ---------------------------------------------------------------------------
__global__ __launch_bounds__(256) void norm_kernel(const float* __restrict__ sinks,
                                                   float* __restrict__ out) {
    const int row = blockIdx.x;
    const int i = row & (Sc - 1);
    const float es = __expf(sinks[row]);
    const float Z = g_rowsum[row] + (float)(Sc - 1 - i) + es;
    const float invZ = 1.0f / Z;
    float* orow = out + (size_t)row * SP1;
    for (int j = threadIdx.x; j <= Sc; j += 256) {
        float v;
        if (j <= i)      v = orow[j] * invZ;
        else if (j < Sc) v = invZ;
        else             v = es * invZ;
        orow[j] = v;
    }
}

// ---------------------------------------------------------------------------
extern "C" void kernel_launch(void* const* d_in, const int* in_sizes, int n_in,
                              void* d_out, int out_size) {
    const float* q     = (const float*)d_in[0];
    const float* k     = (const float*)d_in[1];
    const float* sinks = (const float*)d_in[2];
    float* out = (float*)d_out;
    (void)in_sizes; (void)n_in; (void)out_size;

    prep_kernel<<<NROWS / 256, 256>>>(k);
    dim3 grid(NTILES, Bc * Hc);
    scores_kernel<<<grid, 256>>>(q, k, out);
    norm_kernel<<<NROWS, 256>>>(sinks, out);
}

// round 5
// speedup vs baseline: 1.4875x; 1.4875x over previous
#include <cuda_runtime.h>
#include <cuda_bf16.h>
#include <cstdint>

#define Bc 2
#define Hc 16
#define Sc 2048
#define Dc 64
#define NROWS (Bc * Hc * Sc)   // 65536
#define SP1 (Sc + 1)           // 2049
#define NT128 136              // 16*17/2 causal 128x128 tile pairs

// Scratch: per-key log2e/||k|| and softmax partial sums.
__device__ float g_invn[NROWS];
__device__ float g_rowsum[NROWS];

// ---------------------------------------------------------------------------
// helpers
// ---------------------------------------------------------------------------
__device__ __forceinline__ uint32_t smem_u32(const void* p) {
    uint32_t a;
    asm("{ .reg .u64 t; cvta.to.shared.u64 t, %1; cvt.u32.u64 %0, t; }" : "=r"(a) : "l"(p));
    return a;
}
__device__ __forceinline__ float ex2f(float x) {
    float r; asm("ex2.approx.f32 %0, %1;" : "=f"(r) : "f"(x)); return r;
}
__device__ __forceinline__ void ldsm_x4(uint32_t a, uint32_t& r0, uint32_t& r1,
                                        uint32_t& r2, uint32_t& r3) {
    asm volatile("ldmatrix.sync.aligned.m8n8.x4.shared.b16 {%0,%1,%2,%3}, [%4];"
                 : "=r"(r0), "=r"(r1), "=r"(r2), "=r"(r3) : "r"(a));
}
__device__ __forceinline__ void ldsm_x2(uint32_t a, uint32_t& r0, uint32_t& r1) {
    asm volatile("ldmatrix.sync.aligned.m8n8.x2.shared.b16 {%0,%1}, [%2];"
                 : "=r"(r0), "=r"(r1) : "r"(a));
}
__device__ __forceinline__ void mma_bf16(float* d, const uint32_t* a, const uint32_t* b) {
    asm volatile(
        "mma.sync.aligned.m16n8k16.row.col.f32.bf16.bf16.f32 "
        "{%0,%1,%2,%3}, {%4,%5,%6,%7}, {%8,%9}, {%0,%1,%2,%3};"
        : "+f"(d[0]), "+f"(d[1]), "+f"(d[2]), "+f"(d[3])
        : "r"(a[0]), "r"(a[1]), "r"(a[2]), "r"(a[3]), "r"(b[0]), "r"(b[1]));
}

// smem tiles: [128 rows][72 bf16] (144B padded rows -> ldmatrix conflict-free)
#define TROW 72
#define TBYTES (128 * TROW * 2)          // 18432
#define OFF_QH 0
#define OFF_QL (1 * TBYTES)
#define OFF_KH (2 * TBYTES)
#define OFF_KL (3 * TBYTES)
#define SMEM_SZ (4 * TBYTES)             // 73728

// ---------------------------------------------------------------------------
// Kernel 1: per-key log2(e)/||k|| + zero row sums
// ---------------------------------------------------------------------------
__global__ __launch_bounds__(256) void prep_kernel(const float* __restrict__ k) {
    int row = blockIdx.x * blockDim.x + threadIdx.x;
    if (row >= NROWS) return;
    const float4* kr = (const float4*)(k + (size_t)row * Dc);
    float s = 0.f;
#pragma unroll
    for (int i = 0; i < Dc / 4; i++) {
        float4 v = kr[i];
        s += v.x * v.x + v.y * v.y + v.z * v.z + v.w * v.w;
    }
    g_invn[row] = 1.4426950408889634f * rsqrtf(s);
    g_rowsum[row] = 0.f;
}

// ---------------------------------------------------------------------------
// Kernel 2: mma.sync bf16x3-split scores, one 128x128 causal tile per CTA.
// 8 warps = 2(m) x 4(n); warp tile 64x32; accumulators in registers; exp,
// rowsum (REDG) and stores straight from fragments.
// ---------------------------------------------------------------------------
__global__ __launch_bounds__(256) void scores_kernel(const float* __restrict__ q,
                                                     const float* __restrict__ k,
                                                     float* __restrict__ out) {
    extern __shared__ char smem[];
    const uint32_t sb = smem_u32(smem);
    const int t = threadIdx.x;
    const int wid = t >> 5;
    const int lane = t & 31;

    // triangular decode p -> (qt, kt), kt <= qt (128-granularity)
    const int p = blockIdx.x;
    int qt = (int)((sqrtf(8.0f * (float)p + 1.0f) - 1.0f) * 0.5f);
    while ((qt + 1) * (qt + 2) / 2 <= p) qt++;
    while (qt * (qt + 1) / 2 > p) qt--;
    const int kt = p - qt * (qt + 1) / 2;
    const bool diag = (kt == qt);

    const int bh = blockIdx.y;
    const int i0 = qt * 128;
    const int j0 = kt * 128;
    const size_t base = (size_t)bh * Sc;

    // Stage Q (hi/lo) and scaled-K (hi/lo) as bf16, padded rows.
    {
        const float4* qg = (const float4*)(q + (base + i0) * Dc);
        const float4* kg = (const float4*)(k + (base + j0) * Dc);
#pragma unroll
        for (int it = 0; it < 8; it++) {
            int idx = t + 256 * it;           // 0..2047
            int row = idx >> 4, c4 = idx & 15;
            uint32_t so = (row * TROW + c4 * 4) * 2;   // byte offset
            {
                float4 v = qg[row * 16 + c4];
                union { __nv_bfloat16 b[4]; unsigned long long u; } H, L;
#pragma unroll
                for (int e = 0; e < 4; e++) {
                    float x = (&v.x)[e];
                    __nv_bfloat16 h = __float2bfloat16_rn(x);
                    H.b[e] = h;
                    L.b[e] = __float2bfloat16_rn(x - __bfloat162float(h));
                }
                *(unsigned long long*)(smem + OFF_QH + so) = H.u;
                *(unsigned long long*)(smem + OFF_QL + so) = L.u;
            }
            {
                float s = g_invn[base + j0 + row];
                float4 v = kg[row * 16 + c4];
                union { __nv_bfloat16 b[4]; unsigned long long u; } H, L;
#pragma unroll
                for (int e = 0; e < 4; e++) {
                    float x = (&v.x)[e] * s;
                    __nv_bfloat16 h = __float2bfloat16_rn(x);
                    H.b[e] = h;
                    L.b[e] = __float2bfloat16_rn(x - __bfloat162float(h));
                }
                *(unsigned long long*)(smem + OFF_KH + so) = H.u;
                *(unsigned long long*)(smem + OFF_KL + so) = L.u;
            }
        }
    }
    __syncthreads();

    const int wm = wid >> 2;           // 0..1 -> m offset 64*wm
    const int wn = wid & 3;            // 0..3 -> n offset 32*wn

    float acc[4][4][4];
#pragma unroll
    for (int mt = 0; mt < 4; mt++)
#pragma unroll
        for (int nt = 0; nt < 4; nt++)
#pragma unroll
            for (int e = 0; e < 4; e++) acc[mt][nt][e] = 0.f;

    // ldmatrix lane-address components
    const int a_row = (lane & 7) + ((lane >> 3) & 1) * 8;   // row within 16
    const int a_colb = (lane >> 4) * 8;                     // k sub-block
    const int b_row = lane & 7;
    const int b_colb = ((lane >> 3) & 1) * 8;

    const uint32_t aBases[3] = { sb + OFF_QH, sb + OFF_QL, sb + OFF_QH };
    const uint32_t bBases[3] = { sb + OFF_KH, sb + OFF_KH, sb + OFF_KL };

#pragma unroll
    for (int pass = 0; pass < 3; pass++) {
        const uint32_t aB = aBases[pass], bB = bBases[pass];
#pragma unroll
        for (int ks = 0; ks < 4; ks++) {
            uint32_t a[4][4], b[4][2];
#pragma unroll
            for (int mt = 0; mt < 4; mt++) {
                uint32_t addr = aB +
                    ((wm * 64 + mt * 16 + a_row) * TROW + ks * 16 + a_colb) * 2;
                ldsm_x4(addr, a[mt][0], a[mt][1], a[mt][2], a[mt][3]);
            }
#pragma unroll
            for (int nt = 0; nt < 4; nt++) {
                uint32_t addr = bB +
                    ((wn * 32 + nt * 8 + b_row) * TROW + ks * 16 + b_colb) * 2;
                ldsm_x2(addr, b[nt][0], b[nt][1]);
            }
#pragma unroll
            for (int mt = 0; mt < 4; mt++)
#pragma unroll
                for (int nt = 0; nt < 4; nt++)
                    mma_bf16(acc[mt][nt], a[mt], b[nt]);
        }
    }

    // Epilogue: exp (log2 domain), causal mask, rowsum REDG, scalar stores.
    const int qrow = lane >> 2;          // 0..7
    const int cpair = (lane & 3) * 2;
#pragma unroll
    for (int mt = 0; mt < 4; mt++) {
        const int r0l = wm * 64 + mt * 16 + qrow;   // local rows
        const int r1l = r0l + 8;
        const size_t orow0 = (base + (size_t)(i0 + r0l)) * SP1 + j0;
        const size_t orow1 = (base + (size_t)(i0 + r1l)) * SP1 + j0;
        float s0 = 0.f, s1 = 0.f;
#pragma unroll
        for (int nt = 0; nt < 4; nt++) {
            const int c = wn * 32 + nt * 8 + cpair; // local col (c, c+1)
            float* d = acc[mt][nt];
            if (!diag || c <= r0l) {
                float e = ex2f(d[0]); s0 += e; out[orow0 + c] = e;
            }
            if (!diag || c + 1 <= r0l) {
                float e = ex2f(d[1]); s0 += e; out[orow0 + c + 1] = e;
            }
            if (!diag || c <= r1l) {
                float e = ex2f(d[2]); s1 += e; out[orow1 + c] = e;
            }
            if (!diag || c + 1 <= r1l) {
                float e = ex2f(d[3]); s1 += e; out[orow1 + c + 1] = e;
            }
        }
        s0 += __shfl_xor_sync(0xffffffffu, s0, 1);
        s0 += __shfl_xor_sync(0xffffffffu, s0, 2);
        s1 += __shfl_xor_sync(0xffffffffu, s1, 1);
        s1 += __shfl_xor_sync(0xffffffffu, s1, 2);
        if ((lane & 3) == 0) {
            atomicAdd(&g_rowsum[base + i0 + r0l], s0);
            atomicAdd(&g_rowsum[base + i0 + r1l], s1);
        }
    }
}

// ---------------------------------------------------------------------------
// Kernel 3: normalize. Z = rowsum + (S-1-i) + exp(sink).
// ---------------------------------------------------------------------------
__global__ __launch_bounds__(256) void norm_kernel(const float* __restrict__ sinks,
                                                   float* __restrict__ out) {
    const int row = blockIdx.x;
    const int i = row & (Sc - 1);
    const float es = __expf(sinks[row]);
    const float Z = g_rowsum[row] + (float)(Sc - 1 - i) + es;
    const float invZ = 1.0f / Z;
    float* orow = out + (size_t)row * SP1;
    for (int j = threadIdx.x; j <= Sc; j += 256) {
        float v;
        if (j <= i)      v = orow[j] * invZ;
        else if (j < Sc) v = invZ;
        else             v = es * invZ;
        orow[j] = v;
    }
}

// ---------------------------------------------------------------------------
extern "C" void kernel_launch(void* const* d_in, const int* in_sizes, int n_in,
                              void* d_out, int out_size) {
    const float* q     = (const float*)d_in[0];
    const float* k     = (const float*)d_in[1];
    const float* sinks = (const float*)d_in[2];
    float* out = (float*)d_out;
    (void)in_sizes; (void)n_in; (void)out_size;

    cudaFuncSetAttribute(scores_kernel, cudaFuncAttributeMaxDynamicSharedMemorySize, SMEM_SZ);

    prep_kernel<<<NROWS / 256, 256>>>(k);
    dim3 grid(NT128, Bc * Hc);
    scores_kernel<<<grid, 256, SMEM_SZ>>>(q, k, out);
    norm_kernel<<<NROWS, 256>>>(sinks, out);
}

// round 9
// speedup vs baseline: 1.5595x; 1.0484x over previous
#include <cuda_runtime.h>
#include <cuda_bf16.h>
#include <cstdint>

#define Bc 2
#define Hc 16
#define Sc 2048
#define Dc 64
#define NROWS (Bc * Hc * Sc)   // 65536
#define SP1 (Sc + 1)           // 2049
#define NT128 136              // 16*17/2 causal 128x128 tile pairs

// Scratch
__device__ float g_invn[NROWS];    // log2e / ||k||
__device__ float g_rowsum[NROWS];  // sum of exps over lower triangle
__device__ float g_invz[NROWS];    // 1/Z

// ---------------------------------------------------------------------------
// helpers
// ---------------------------------------------------------------------------
__device__ __forceinline__ uint32_t smem_u32(const void* p) {
    uint32_t a;
    asm("{ .reg .u64 t; cvta.to.shared.u64 t, %1; cvt.u32.u64 %0, t; }" : "=r"(a) : "l"(p));
    return a;
}
__device__ __forceinline__ float ex2f(float x) {
    float r; asm("ex2.approx.f32 %0, %1;" : "=f"(r) : "f"(x)); return r;
}
__device__ __forceinline__ void ldsm_x4(uint32_t a, uint32_t& r0, uint32_t& r1,
                                        uint32_t& r2, uint32_t& r3) {
    asm volatile("ldmatrix.sync.aligned.m8n8.x4.shared.b16 {%0,%1,%2,%3}, [%4];"
                 : "=r"(r0), "=r"(r1), "=r"(r2), "=r"(r3) : "r"(a));
}
__device__ __forceinline__ void ldsm_x2(uint32_t a, uint32_t& r0, uint32_t& r1) {
    asm volatile("ldmatrix.sync.aligned.m8n8.x2.shared.b16 {%0,%1}, [%2];"
                 : "=r"(r0), "=r"(r1) : "r"(a));
}
__device__ __forceinline__ void mma_bf16(float* d, const uint32_t* a, const uint32_t* b) {
    asm volatile(
        "mma.sync.aligned.m16n8k16.row.col.f32.bf16.bf16.f32 "
        "{%0,%1,%2,%3}, {%4,%5,%6,%7}, {%8,%9}, {%0,%1,%2,%3};"
        : "+f"(d[0]), "+f"(d[1]), "+f"(d[2]), "+f"(d[3])
        : "r"(a[0]), "r"(a[1]), "r"(a[2]), "r"(a[3]), "r"(b[0]), "r"(b[1]));
}

// smem tiles: [128 rows][72 bf16] (144B padded rows -> ldmatrix conflict-free)
#define TROW 72
#define TBYTES (128 * TROW * 2)          // 18432
#define OFF_QH 0
#define OFF_QL (1 * TBYTES)
#define OFF_KH (2 * TBYTES)
#define OFF_KL (3 * TBYTES)
#define SMEM_SZ (4 * TBYTES)             // 73728

// ---------------------------------------------------------------------------
// Kernel 1: per-key log2(e)/||k|| + zero row sums
// ---------------------------------------------------------------------------
__global__ __launch_bounds__(256) void prep_kernel(const float* __restrict__ k) {
    int row = blockIdx.x * blockDim.x + threadIdx.x;
    if (row >= NROWS) return;
    const float4* kr = (const float4*)(k + (size_t)row * Dc);
    float s = 0.f;
#pragma unroll
    for (int i = 0; i < Dc / 4; i++) {
        float4 v = kr[i];
        s += v.x * v.x + v.y * v.y + v.z * v.z + v.w * v.w;
    }
    g_invn[row] = 1.4426950408889634f * rsqrtf(s);
    g_rowsum[row] = 0.f;
}

// ---------------------------------------------------------------------------
// Shared tile machinery: stage Q/K (bf16 hi/lo) and run the 3-pass GEMM.
// ---------------------------------------------------------------------------
__device__ __forceinline__ void stage_tiles(char* smem, const float* __restrict__ q,
                                            const float* __restrict__ k,
                                            size_t base, int i0, int j0, int t) {
    const float4* qg = (const float4*)(q + (base + i0) * Dc);
    const float4* kg = (const float4*)(k + (base + j0) * Dc);
#pragma unroll
    for (int it = 0; it < 8; it++) {
        int idx = t + 256 * it;           // 0..2047
        int row = idx >> 4, c4 = idx & 15;
        uint32_t so = (row * TROW + c4 * 4) * 2;
        {
            float4 v = qg[row * 16 + c4];
            union { __nv_bfloat16 b[4]; unsigned long long u; } H, L;
#pragma unroll
            for (int e = 0; e < 4; e++) {
                float x = (&v.x)[e];
                __nv_bfloat16 h = __float2bfloat16_rn(x);
                H.b[e] = h;
                L.b[e] = __float2bfloat16_rn(x - __bfloat162float(h));
            }
            *(unsigned long long*)(smem + OFF_QH + so) = H.u;
            *(unsigned long long*)(smem + OFF_QL + so) = L.u;
        }
        {
            float s = g_invn[base + j0 + row];
            float4 v = kg[row * 16 + c4];
            union { __nv_bfloat16 b[4]; unsigned long long u; } H, L;
#pragma unroll
            for (int e = 0; e < 4; e++) {
                float x = (&v.x)[e] * s;
                __nv_bfloat16 h = __float2bfloat16_rn(x);
                H.b[e] = h;
                L.b[e] = __float2bfloat16_rn(x - __bfloat162float(h));
            }
            *(unsigned long long*)(smem + OFF_KH + so) = H.u;
            *(unsigned long long*)(smem + OFF_KL + so) = L.u;
        }
    }
}

__device__ __forceinline__ void compute_acc(uint32_t sb, int wm, int wn, int lane,
                                            float acc[4][4][4]) {
#pragma unroll
    for (int mt = 0; mt < 4; mt++)
#pragma unroll
        for (int nt = 0; nt < 4; nt++)
#pragma unroll
            for (int e = 0; e < 4; e++) acc[mt][nt][e] = 0.f;

    const int a_row = (lane & 7) + ((lane >> 3) & 1) * 8;
    const int a_colb = (lane >> 4) * 8;
    const int b_row = lane & 7;
    const int b_colb = ((lane >> 3) & 1) * 8;

    const uint32_t aBases[3] = { sb + OFF_QH, sb + OFF_QL, sb + OFF_QH };
    const uint32_t bBases[3] = { sb + OFF_KH, sb + OFF_KH, sb + OFF_KL };

#pragma unroll
    for (int pass = 0; pass < 3; pass++) {
        const uint32_t aB = aBases[pass], bB = bBases[pass];
#pragma unroll
        for (int ks = 0; ks < 4; ks++) {
            uint32_t a[4][4], b[4][2];
#pragma unroll
            for (int mt = 0; mt < 4; mt++) {
                uint32_t addr = aB +
                    ((wm * 64 + mt * 16 + a_row) * TROW + ks * 16 + a_colb) * 2;
                ldsm_x4(addr, a[mt][0], a[mt][1], a[mt][2], a[mt][3]);
            }
#pragma unroll
            for (int nt = 0; nt < 4; nt++) {
                uint32_t addr = bB +
                    ((wn * 32 + nt * 8 + b_row) * TROW + ks * 16 + b_colb) * 2;
                ldsm_x2(addr, b[nt][0], b[nt][1]);
            }
#pragma unroll
            for (int mt = 0; mt < 4; mt++)
#pragma unroll
                for (int nt = 0; nt < 4; nt++)
                    mma_bf16(acc[mt][nt], a[mt], b[nt]);
        }
    }
}

// triangular decode p -> (qt, kt), kt <= qt
__device__ __forceinline__ void tri_decode(int p, int& qt, int& kt) {
    qt = (int)((sqrtf(8.0f * (float)p + 1.0f) - 1.0f) * 0.5f);
    while ((qt + 1) * (qt + 2) / 2 <= p) qt++;
    while (qt * (qt + 1) / 2 > p) qt--;
    kt = p - qt * (qt + 1) / 2;
}

// ---------------------------------------------------------------------------
// Pass A: row sums only (no large stores).
// ---------------------------------------------------------------------------
__global__ __launch_bounds__(256) void sums_kernel(const float* __restrict__ q,
                                                   const float* __restrict__ k) {
    extern __shared__ char smem[];
    const uint32_t sb = smem_u32(smem);
    const int t = threadIdx.x, wid = t >> 5, lane = t & 31;

    int qt, kt;
    tri_decode(blockIdx.x, qt, kt);
    const bool diag = (kt == qt);
    const int bh = blockIdx.y;
    const int i0 = qt * 128, j0 = kt * 128;
    const size_t base = (size_t)bh * Sc;

    stage_tiles(smem, q, k, base, i0, j0, t);
    __syncthreads();

    const int wm = wid >> 2, wn = wid & 3;
    float acc[4][4][4];
    compute_acc(sb, wm, wn, lane, acc);

    const int qrow = lane >> 2;
    const int cpair = (lane & 3) * 2;
#pragma unroll
    for (int mt = 0; mt < 4; mt++) {
        const int r0l = wm * 64 + mt * 16 + qrow;
        const int r1l = r0l + 8;
        float s0 = 0.f, s1 = 0.f;
#pragma unroll
        for (int nt = 0; nt < 4; nt++) {
            const int c = wn * 32 + nt * 8 + cpair;
            float* d = acc[mt][nt];
            if (!diag || c <= r0l)     s0 += ex2f(d[0]);
            if (!diag || c + 1 <= r0l) s0 += ex2f(d[1]);
            if (!diag || c <= r1l)     s1 += ex2f(d[2]);
            if (!diag || c + 1 <= r1l) s1 += ex2f(d[3]);
        }
        s0 += __shfl_xor_sync(0xffffffffu, s0, 1);
        s0 += __shfl_xor_sync(0xffffffffu, s0, 2);
        s1 += __shfl_xor_sync(0xffffffffu, s1, 1);
        s1 += __shfl_xor_sync(0xffffffffu, s1, 2);
        if ((lane & 3) == 0) {
            atomicAdd(&g_rowsum[base + i0 + r0l], s0);
            atomicAdd(&g_rowsum[base + i0 + r1l], s1);
        }
    }
}

// ---------------------------------------------------------------------------
// zfin: invZ per row + write the sink column of out.
// ---------------------------------------------------------------------------
__global__ __launch_bounds__(256) void zfin_kernel(const float* __restrict__ sinks,
                                                   float* __restrict__ out) {
    int row = blockIdx.x * blockDim.x + threadIdx.x;
    if (row >= NROWS) return;
    const int i = row & (Sc - 1);
    const float es = __expf(sinks[row]);
    const float invZ = 1.0f / (g_rowsum[row] + (float)(Sc - 1 - i) + es);
    g_invz[row] = invZ;
    out[(size_t)row * SP1 + Sc] = es * invZ;
}

// ---------------------------------------------------------------------------
// Pass B: final writes. Full 16x16 tile grid; kt>qt tiles are pure fills,
// kt<=qt tiles recompute the GEMM and write e*invZ (diag fills upper w/ invZ).
// ---------------------------------------------------------------------------
__global__ __launch_bounds__(256) void write_kernel(const float* __restrict__ q,
                                                    const float* __restrict__ k,
                                                    float* __restrict__ out) {
    extern __shared__ char smem[];
    const uint32_t sb = smem_u32(smem);
    const int t = threadIdx.x, wid = t >> 5, lane = t & 31;

    const int qt = blockIdx.x >> 4;
    const int kt = blockIdx.x & 15;
    const int bh = blockIdx.y;
    const int i0 = qt * 128, j0 = kt * 128;
    const size_t base = (size_t)bh * Sc;

    if (kt > qt) {   // pure fill: out = invZ (fully masked tile)
        for (int idx = t; idx < 128 * 128; idx += 256) {
            const int r = idx >> 7, c = idx & 127;
            const float invZ = g_invz[base + i0 + r];   // warp-uniform -> L1 hit
            out[(base + (size_t)(i0 + r)) * SP1 + j0 + c] = invZ;
        }
        return;
    }

    const bool diag = (kt == qt);
    stage_tiles(smem, q, k, base, i0, j0, t);
    __syncthreads();

    const int wm = wid >> 2, wn = wid & 3;
    float acc[4][4][4];
    compute_acc(sb, wm, wn, lane, acc);

    const int qrow = lane >> 2;
    const int cpair = (lane & 3) * 2;
#pragma unroll
    for (int mt = 0; mt < 4; mt++) {
        const int r0l = wm * 64 + mt * 16 + qrow;
        const int r1l = r0l + 8;
        const float iz0 = g_invz[base + i0 + r0l];
        const float iz1 = g_invz[base + i0 + r1l];
        const size_t orow0 = (base + (size_t)(i0 + r0l)) * SP1 + j0;
        const size_t orow1 = (base + (size_t)(i0 + r1l)) * SP1 + j0;
#pragma unroll
        for (int nt = 0; nt < 4; nt++) {
            const int c = wn * 32 + nt * 8 + cpair;
            float* d = acc[mt][nt];
            out[orow0 + c]     = (!diag || c <= r0l)     ? ex2f(d[0]) * iz0 : iz0;
            out[orow0 + c + 1] = (!diag || c + 1 <= r0l) ? ex2f(d[1]) * iz0 : iz0;
            out[orow1 + c]     = (!diag || c <= r1l)     ? ex2f(d[2]) * iz1 : iz1;
            out[orow1 + c + 1] = (!diag || c + 1 <= r1l) ? ex2f(d[3]) * iz1 : iz1;
        }
    }
}

// ---------------------------------------------------------------------------
extern "C" void kernel_launch(void* const* d_in, const int* in_sizes, int n_in,
                              void* d_out, int out_size) {
    const float* q     = (const float*)d_in[0];
    const float* k     = (const float*)d_in[1];
    const float* sinks = (const float*)d_in[2];
    float* out = (float*)d_out;
    (void)in_sizes; (void)n_in; (void)out_size;

    cudaFuncSetAttribute(sums_kernel, cudaFuncAttributeMaxDynamicSharedMemorySize, SMEM_SZ);
    cudaFuncSetAttribute(write_kernel, cudaFuncAttributeMaxDynamicSharedMemorySize, SMEM_SZ);

    prep_kernel<<<NROWS / 256, 256>>>(k);
    sums_kernel<<<dim3(NT128, Bc * Hc), 256, SMEM_SZ>>>(q, k);
    zfin_kernel<<<NROWS / 256, 256>>>(sinks, out);
    write_kernel<<<dim3(256, Bc * Hc), 256, SMEM_SZ>>>(q, k, out);
}

// round 10
// speedup vs baseline: 2.2084x; 1.4162x over previous
#include <cuda_runtime.h>
#include <cuda_bf16.h>
#include <cstdint>

#define Bc 2
#define Hc 16
#define Sc 2048
#define Dc 64
#define NROWS (Bc * Hc * Sc)   // 65536
#define SP1 (Sc + 1)           // 2049
#define NT128 136              // 16*17/2 causal 128x128 tile pairs
#define NFILL 120              // 15*16/2 strictly-masked tile pairs

// Scratch
__device__ float g_invn[NROWS];    // log2e / ||k||
__device__ float g_rowsum[NROWS];  // sum of exps over lower triangle
__device__ float g_invz[NROWS];    // 1/Z

// ---------------------------------------------------------------------------
// helpers
// ---------------------------------------------------------------------------
__device__ __forceinline__ uint32_t smem_u32(const void* p) {
    uint32_t a;
    asm("{ .reg .u64 t; cvta.to.shared.u64 t, %1; cvt.u32.u64 %0, t; }" : "=r"(a) : "l"(p));
    return a;
}
__device__ __forceinline__ float ex2f(float x) {
    float r; asm("ex2.approx.f32 %0, %1;" : "=f"(r) : "f"(x)); return r;
}
__device__ __forceinline__ void stcs(float* p, float v) {
    asm volatile("st.global.cs.f32 [%0], %1;" :: "l"(p), "f"(v) : "memory");
}
__device__ __forceinline__ void ldsm_x4(uint32_t a, uint32_t& r0, uint32_t& r1,
                                        uint32_t& r2, uint32_t& r3) {
    asm volatile("ldmatrix.sync.aligned.m8n8.x4.shared.b16 {%0,%1,%2,%3}, [%4];"
                 : "=r"(r0), "=r"(r1), "=r"(r2), "=r"(r3) : "r"(a));
}
__device__ __forceinline__ void ldsm_x2(uint32_t a, uint32_t& r0, uint32_t& r1) {
    asm volatile("ldmatrix.sync.aligned.m8n8.x2.shared.b16 {%0,%1}, [%2];"
                 : "=r"(r0), "=r"(r1) : "r"(a));
}
__device__ __forceinline__ void mma_bf16(float* d, const uint32_t* a, const uint32_t* b) {
    asm volatile(
        "mma.sync.aligned.m16n8k16.row.col.f32.bf16.bf16.f32 "
        "{%0,%1,%2,%3}, {%4,%5,%6,%7}, {%8,%9}, {%0,%1,%2,%3};"
        : "+f"(d[0]), "+f"(d[1]), "+f"(d[2]), "+f"(d[3])
        : "r"(a[0]), "r"(a[1]), "r"(a[2]), "r"(a[3]), "r"(b[0]), "r"(b[1]));
}

// smem tiles: [128 rows][72 bf16] (144B padded rows -> ldmatrix conflict-free)
#define TROW 72
#define TBYTES (128 * TROW * 2)          // 18432
#define OFF_QH 0
#define OFF_QL (1 * TBYTES)
#define OFF_KH (2 * TBYTES)
#define OFF_KL (3 * TBYTES)
#define SMEM_SZ (4 * TBYTES)             // 73728

// ---------------------------------------------------------------------------
// Kernel 1: per-key log2(e)/||k|| + zero row sums
// ---------------------------------------------------------------------------
__global__ __launch_bounds__(256) void prep_kernel(const float* __restrict__ k) {
    int row = blockIdx.x * blockDim.x + threadIdx.x;
    if (row >= NROWS) return;
    const float4* kr = (const float4*)(k + (size_t)row * Dc);
    float s = 0.f;
#pragma unroll
    for (int i = 0; i < Dc / 4; i++) {
        float4 v = kr[i];
        s += v.x * v.x + v.y * v.y + v.z * v.z + v.w * v.w;
    }
    g_invn[row] = 1.4426950408889634f * rsqrtf(s);
    g_rowsum[row] = 0.f;
}

// ---------------------------------------------------------------------------
// Tile staging: Q/K as bf16 hi/lo (3-term split, log2e folded into K).
// ---------------------------------------------------------------------------
__device__ __forceinline__ void stage_tiles(char* smem, const float* __restrict__ q,
                                            const float* __restrict__ k,
                                            size_t base, int i0, int j0, int t) {
    const float4* qg = (const float4*)(q + (base + i0) * Dc);
    const float4* kg = (const float4*)(k + (base + j0) * Dc);
#pragma unroll
    for (int it = 0; it < 8; it++) {
        int idx = t + 256 * it;           // 0..2047
        int row = idx >> 4, c4 = idx & 15;
        uint32_t so = (row * TROW + c4 * 4) * 2;
        {
            float4 v = qg[row * 16 + c4];
            union { __nv_bfloat16 b[4]; unsigned long long u; } H, L;
#pragma unroll
            for (int e = 0; e < 4; e++) {
                float x = (&v.x)[e];
                __nv_bfloat16 h = __float2bfloat16_rn(x);
                H.b[e] = h;
                L.b[e] = __float2bfloat16_rn(x - __bfloat162float(h));
            }
            *(unsigned long long*)(smem + OFF_QH + so) = H.u;
            *(unsigned long long*)(smem + OFF_QL + so) = L.u;
        }
        {
            float s = g_invn[base + j0 + row];
            float4 v = kg[row * 16 + c4];
            union { __nv_bfloat16 b[4]; unsigned long long u; } H, L;
#pragma unroll
            for (int e = 0; e < 4; e++) {
                float x = (&v.x)[e] * s;
                __nv_bfloat16 h = __float2bfloat16_rn(x);
                H.b[e] = h;
                L.b[e] = __float2bfloat16_rn(x - __bfloat162float(h));
            }
            *(unsigned long long*)(smem + OFF_KH + so) = H.u;
            *(unsigned long long*)(smem + OFF_KL + so) = L.u;
        }
    }
}

// GEMM for one N-half (16 cols of the warp's 32): acc[4][2][4] = 32 regs live.
__device__ __forceinline__ void compute_half(uint32_t sb, int wm, int wn, int half,
                                             int lane, float acc[4][2][4]) {
#pragma unroll
    for (int mt = 0; mt < 4; mt++)
#pragma unroll
        for (int nt = 0; nt < 2; nt++)
#pragma unroll
            for (int e = 0; e < 4; e++) acc[mt][nt][e] = 0.f;

    const int a_row = (lane & 7) + ((lane >> 3) & 1) * 8;
    const int a_colb = (lane >> 4) * 8;
    const int b_row = lane & 7;
    const int b_colb = ((lane >> 3) & 1) * 8;
    const int ncol0 = wn * 32 + half * 16;

    const uint32_t aBases[3] = { sb + OFF_QH, sb + OFF_QL, sb + OFF_QH };
    const uint32_t bBases[3] = { sb + OFF_KH, sb + OFF_KH, sb + OFF_KL };

#pragma unroll
    for (int pass = 0; pass < 3; pass++) {
        const uint32_t aB = aBases[pass], bB = bBases[pass];
#pragma unroll
        for (int ks = 0; ks < 4; ks++) {
            uint32_t a[4][4], b[2][2];
#pragma unroll
            for (int mt = 0; mt < 4; mt++) {
                uint32_t addr = aB +
                    ((wm * 64 + mt * 16 + a_row) * TROW + ks * 16 + a_colb) * 2;
                ldsm_x4(addr, a[mt][0], a[mt][1], a[mt][2], a[mt][3]);
            }
#pragma unroll
            for (int nt = 0; nt < 2; nt++) {
                uint32_t addr = bB +
                    ((ncol0 + nt * 8 + b_row) * TROW + ks * 16 + b_colb) * 2;
                ldsm_x2(addr, b[nt][0], b[nt][1]);
            }
#pragma unroll
            for (int mt = 0; mt < 4; mt++)
#pragma unroll
                for (int nt = 0; nt < 2; nt++)
                    mma_bf16(acc[mt][nt], a[mt], b[nt]);
        }
    }
}

// triangular decode p -> (a, b), b <= a
__device__ __forceinline__ void tri_decode(int p, int& a, int& b) {
    a = (int)((sqrtf(8.0f * (float)p + 1.0f) - 1.0f) * 0.5f);
    while ((a + 1) * (a + 2) / 2 <= p) a++;
    while (a * (a + 1) / 2 > p) a--;
    b = p - a * (a + 1) / 2;
}

// ---------------------------------------------------------------------------
// Pass A: row sums only (no large stores). N-halved for register pressure.
// ---------------------------------------------------------------------------
__global__ __launch_bounds__(256, 2) void sums_kernel(const float* __restrict__ q,
                                                      const float* __restrict__ k) {
    extern __shared__ char smem[];
    const uint32_t sb = smem_u32(smem);
    const int t = threadIdx.x, wid = t >> 5, lane = t & 31;

    int qt, kt;
    tri_decode(blockIdx.x, qt, kt);
    const bool diag = (kt == qt);
    const int bh = blockIdx.y;
    const int i0 = qt * 128, j0 = kt * 128;
    const size_t base = (size_t)bh * Sc;

    stage_tiles(smem, q, k, base, i0, j0, t);
    __syncthreads();

    const int wm = wid >> 2, wn = wid & 3;
    const int qrow = lane >> 2;
    const int cpair = (lane & 3) * 2;

    float rs0[4], rs1[4];
#pragma unroll
    for (int mt = 0; mt < 4; mt++) { rs0[mt] = 0.f; rs1[mt] = 0.f; }

#pragma unroll
    for (int half = 0; half < 2; half++) {
        float acc[4][2][4];
        compute_half(sb, wm, wn, half, lane, acc);
#pragma unroll
        for (int mt = 0; mt < 4; mt++) {
            const int r0l = wm * 64 + mt * 16 + qrow;
            const int r1l = r0l + 8;
#pragma unroll
            for (int nt = 0; nt < 2; nt++) {
                const int c = wn * 32 + half * 16 + nt * 8 + cpair;
                float* d = acc[mt][nt];
                if (!diag || c <= r0l)     rs0[mt] += ex2f(d[0]);
                if (!diag || c + 1 <= r0l) rs0[mt] += ex2f(d[1]);
                if (!diag || c <= r1l)     rs1[mt] += ex2f(d[2]);
                if (!diag || c + 1 <= r1l) rs1[mt] += ex2f(d[3]);
            }
        }
    }

#pragma unroll
    for (int mt = 0; mt < 4; mt++) {
        const int r0l = wm * 64 + mt * 16 + qrow;
        float s0 = rs0[mt], s1 = rs1[mt];
        s0 += __shfl_xor_sync(0xffffffffu, s0, 1);
        s0 += __shfl_xor_sync(0xffffffffu, s0, 2);
        s1 += __shfl_xor_sync(0xffffffffu, s1, 1);
        s1 += __shfl_xor_sync(0xffffffffu, s1, 2);
        if ((lane & 3) == 0) {
            atomicAdd(&g_rowsum[base + i0 + r0l], s0);
            atomicAdd(&g_rowsum[base + i0 + r0l + 8], s1);
        }
    }
}

// ---------------------------------------------------------------------------
// zfin: invZ per row + write the sink column of out.
// ---------------------------------------------------------------------------
__global__ __launch_bounds__(256) void zfin_kernel(const float* __restrict__ sinks,
                                                   float* __restrict__ out) {
    int row = blockIdx.x * blockDim.x + threadIdx.x;
    if (row >= NROWS) return;
    const int i = row & (Sc - 1);
    const float es = __expf(sinks[row]);
    const float invZ = 1.0f / (g_rowsum[row] + (float)(Sc - 1 - i) + es);
    g_invz[row] = invZ;
    out[(size_t)row * SP1 + Sc] = es * invZ;
}

// ---------------------------------------------------------------------------
// Fill kernel: strictly-masked tiles (kt > qt), out = invZ. Featherweight:
// no smem, few regs -> full occupancy, pure streaming stores.
// ---------------------------------------------------------------------------
__global__ __launch_bounds__(256) void fill_kernel(float* __restrict__ out) {
    int a, b;
    tri_decode(blockIdx.x, a, b);     // a in [0,15), b <= a
    const int kt = a + 1;             // kt in [1,16)
    const int qt = b;                 // qt < kt
    const int bh = blockIdx.y;
    const int i0 = qt * 128, j0 = kt * 128;
    const size_t base = (size_t)bh * Sc;
    const int t = threadIdx.x;

#pragma unroll
    for (int it = 0; it < 64; it++) {
        const int idx = t + 256 * it;
        const int r = idx >> 7, c = idx & 127;
        const float invZ = g_invz[base + i0 + r];   // warp-uniform
        stcs(&out[(base + (size_t)(i0 + r)) * SP1 + j0 + c], invZ);
    }
}

// ---------------------------------------------------------------------------
// Pass B: causal tiles only. Recompute GEMM, write final e*invZ (diag tiles
// fill their upper part with invZ). N-halved.
// ---------------------------------------------------------------------------
__global__ __launch_bounds__(256, 2) void write_kernel(const float* __restrict__ q,
                                                       const float* __restrict__ k,
                                                       float* __restrict__ out) {
    extern __shared__ char smem[];
    const uint32_t sb = smem_u32(smem);
    const int t = threadIdx.x, wid = t >> 5, lane = t & 31;

    int qt, kt;
    tri_decode(blockIdx.x, qt, kt);
    const bool diag = (kt == qt);
    const int bh = blockIdx.y;
    const int i0 = qt * 128, j0 = kt * 128;
    const size_t base = (size_t)bh * Sc;

    stage_tiles(smem, q, k, base, i0, j0, t);
    __syncthreads();

    const int wm = wid >> 2, wn = wid & 3;
    const int qrow = lane >> 2;
    const int cpair = (lane & 3) * 2;

#pragma unroll
    for (int half = 0; half < 2; half++) {
        float acc[4][2][4];
        compute_half(sb, wm, wn, half, lane, acc);
#pragma unroll
        for (int mt = 0; mt < 4; mt++) {
            const int r0l = wm * 64 + mt * 16 + qrow;
            const int r1l = r0l + 8;
            const float iz0 = g_invz[base + i0 + r0l];
            const float iz1 = g_invz[base + i0 + r1l];
            float* orow0 = out + (base + (size_t)(i0 + r0l)) * SP1 + j0;
            float* orow1 = out + (base + (size_t)(i0 + r1l)) * SP1 + j0;
#pragma unroll
            for (int nt = 0; nt < 2; nt++) {
                const int c = wn * 32 + half * 16 + nt * 8 + cpair;
                float* d = acc[mt][nt];
                stcs(orow0 + c,     (!diag || c <= r0l)     ? ex2f(d[0]) * iz0 : iz0);
                stcs(orow0 + c + 1, (!diag || c + 1 <= r0l) ? ex2f(d[1]) * iz0 : iz0);
                stcs(orow1 + c,     (!diag || c <= r1l)     ? ex2f(d[2]) * iz1 : iz1);
                stcs(orow1 + c + 1, (!diag || c + 1 <= r1l) ? ex2f(d[3]) * iz1 : iz1);
            }
        }
    }
}

// ---------------------------------------------------------------------------
extern "C" void kernel_launch(void* const* d_in, const int* in_sizes, int n_in,
                              void* d_out, int out_size) {
    const float* q     = (const float*)d_in[0];
    const float* k     = (const float*)d_in[1];
    const float* sinks = (const float*)d_in[2];
    float* out = (float*)d_out;
    (void)in_sizes; (void)n_in; (void)out_size;

    cudaFuncSetAttribute(sums_kernel, cudaFuncAttributeMaxDynamicSharedMemorySize, SMEM_SZ);
    cudaFuncSetAttribute(write_kernel, cudaFuncAttributeMaxDynamicSharedMemorySize, SMEM_SZ);

    prep_kernel<<<NROWS / 256, 256>>>(k);
    sums_kernel<<<dim3(NT128, Bc * Hc), 256, SMEM_SZ>>>(q, k);
    zfin_kernel<<<NROWS / 256, 256>>>(sinks, out);
    fill_kernel<<<dim3(NFILL, Bc * Hc), 256>>>(out);
    write_kernel<<<dim3(NT128, Bc * Hc), 256, SMEM_SZ>>>(q, k, out);
}

// round 11
// speedup vs baseline: 2.2444x; 1.0163x over previous
#include <cuda_runtime.h>
#include <cuda_bf16.h>
#include <cstdint>

#define Bc 2
#define Hc 16
#define Sc 2048
#define Dc 64
#define NROWS (Bc * Hc * Sc)   // 65536
#define SP1 (Sc + 1)           // 2049
#define NT128 136              // 16*17/2 causal 128x128 tile pairs
#define NFILL 120              // 15*16/2 strictly-masked tile pairs

// Scratch
__device__ float g_invn[NROWS];    // log2e / ||k||
__device__ float g_rowsum[NROWS];  // sum of exps over lower triangle
__device__ float g_invz[NROWS];    // 1/Z
// Pre-split bf16 operands (hi/lo), K pre-scaled by log2e/||k||.
__device__ __nv_bfloat16 g_qh[NROWS * Dc];
__device__ __nv_bfloat16 g_ql[NROWS * Dc];
__device__ __nv_bfloat16 g_kh[NROWS * Dc];
__device__ __nv_bfloat16 g_kl[NROWS * Dc];

// ---------------------------------------------------------------------------
// helpers
// ---------------------------------------------------------------------------
__device__ __forceinline__ uint32_t smem_u32(const void* p) {
    uint32_t a;
    asm("{ .reg .u64 t; cvta.to.shared.u64 t, %1; cvt.u32.u64 %0, t; }" : "=r"(a) : "l"(p));
    return a;
}
__device__ __forceinline__ float ex2f(float x) {
    float r; asm("ex2.approx.f32 %0, %1;" : "=f"(r) : "f"(x)); return r;
}
__device__ __forceinline__ void stcs(float* p, float v) {
    asm volatile("st.global.cs.f32 [%0], %1;" :: "l"(p), "f"(v) : "memory");
}
__device__ __forceinline__ void stcs4(float* p, float v) {
    asm volatile("st.global.cs.v4.f32 [%0], {%1,%1,%1,%1};" :: "l"(p), "f"(v) : "memory");
}
__device__ __forceinline__ void ldsm_x4(uint32_t a, uint32_t& r0, uint32_t& r1,
                                        uint32_t& r2, uint32_t& r3) {
    asm volatile("ldmatrix.sync.aligned.m8n8.x4.shared.b16 {%0,%1,%2,%3}, [%4];"
                 : "=r"(r0), "=r"(r1), "=r"(r2), "=r"(r3) : "r"(a));
}
__device__ __forceinline__ void ldsm_x2(uint32_t a, uint32_t& r0, uint32_t& r1) {
    asm volatile("ldmatrix.sync.aligned.m8n8.x2.shared.b16 {%0,%1}, [%2];"
                 : "=r"(r0), "=r"(r1) : "r"(a));
}
__device__ __forceinline__ void mma_bf16(float* d, const uint32_t* a, const uint32_t* b) {
    asm volatile(
        "mma.sync.aligned.m16n8k16.row.col.f32.bf16.bf16.f32 "
        "{%0,%1,%2,%3}, {%4,%5,%6,%7}, {%8,%9}, {%0,%1,%2,%3};"
        : "+f"(d[0]), "+f"(d[1]), "+f"(d[2]), "+f"(d[3])
        : "r"(a[0]), "r"(a[1]), "r"(a[2]), "r"(a[3]), "r"(b[0]), "r"(b[1]));
}

// smem tiles: [128 rows][72 bf16] (144B padded rows -> ldmatrix conflict-free)
#define TROW 72
#define TBYTES (128 * TROW * 2)          // 18432
#define OFF_QH 0
#define OFF_QL (1 * TBYTES)
#define OFF_KH (2 * TBYTES)
#define OFF_KL (3 * TBYTES)
#define SMEM_SZ (4 * TBYTES)             // 73728

// ---------------------------------------------------------------------------
// Kernel 1: per-key log2(e)/||k|| + zero row sums
// ---------------------------------------------------------------------------
__global__ __launch_bounds__(256) void prep_kernel(const float* __restrict__ k) {
    int row = blockIdx.x * blockDim.x + threadIdx.x;
    if (row >= NROWS) return;
    const float4* kr = (const float4*)(k + (size_t)row * Dc);
    float s = 0.f;
#pragma unroll
    for (int i = 0; i < Dc / 4; i++) {
        float4 v = kr[i];
        s += v.x * v.x + v.y * v.y + v.z * v.z + v.w * v.w;
    }
    g_invn[row] = 1.4426950408889634f * rsqrtf(s);
    g_rowsum[row] = 0.f;
}

// ---------------------------------------------------------------------------
// prep2: split Q and scaled-K into global bf16 hi/lo (once, not per tile).
// One thread per (row, 4-col chunk): 65536*16 threads.
// ---------------------------------------------------------------------------
__global__ __launch_bounds__(256) void prep2_kernel(const float* __restrict__ q,
                                                    const float* __restrict__ k) {
    int rc = blockIdx.x * blockDim.x + threadIdx.x;   // 0 .. NROWS*16-1
    int row = rc >> 4, c4 = rc & 15;
    size_t eo = (size_t)row * Dc + c4 * 4;
    {
        float4 v = *(const float4*)(q + eo);
        union { __nv_bfloat16 b[4]; unsigned long long u; } H, L;
#pragma unroll
        for (int e = 0; e < 4; e++) {
            float x = (&v.x)[e];
            __nv_bfloat16 h = __float2bfloat16_rn(x);
            H.b[e] = h;
            L.b[e] = __float2bfloat16_rn(x - __bfloat162float(h));
        }
        *(unsigned long long*)(g_qh + eo) = H.u;
        *(unsigned long long*)(g_ql + eo) = L.u;
    }
    {
        float s = g_invn[row];
        float4 v = *(const float4*)(k + eo);
        union { __nv_bfloat16 b[4]; unsigned long long u; } H, L;
#pragma unroll
        for (int e = 0; e < 4; e++) {
            float x = (&v.x)[e] * s;
            __nv_bfloat16 h = __float2bfloat16_rn(x);
            H.b[e] = h;
            L.b[e] = __float2bfloat16_rn(x - __bfloat162float(h));
        }
        *(unsigned long long*)(g_kh + eo) = H.u;
        *(unsigned long long*)(g_kl + eo) = L.u;
    }
}

// ---------------------------------------------------------------------------
// Tile staging: pure 16B copies from pre-split global bf16 arrays.
// ---------------------------------------------------------------------------
__device__ __forceinline__ void stage_tiles(char* smem, size_t base, int i0, int j0, int t) {
    const uint4* qh = (const uint4*)(g_qh + (base + i0) * Dc);
    const uint4* ql = (const uint4*)(g_ql + (base + i0) * Dc);
    const uint4* kh = (const uint4*)(g_kh + (base + j0) * Dc);
    const uint4* kl = (const uint4*)(g_kl + (base + j0) * Dc);
#pragma unroll
    for (int it = 0; it < 4; it++) {
        int idx = t + 256 * it;           // 0..1023
        int row = idx >> 3, ch = idx & 7; // 8 x 16B chunks per 128B row
        uint32_t so = (row * TROW + ch * 8) * 2;
        int gi = row * 8 + ch;
        *(uint4*)(smem + OFF_QH + so) = qh[gi];
        *(uint4*)(smem + OFF_QL + so) = ql[gi];
        *(uint4*)(smem + OFF_KH + so) = kh[gi];
        *(uint4*)(smem + OFF_KL + so) = kl[gi];
    }
}

// GEMM for one N-half (16 cols of the warp's 32): acc[4][2][4] = 32 regs live.
__device__ __forceinline__ void compute_half(uint32_t sb, int wm, int wn, int half,
                                             int lane, float acc[4][2][4]) {
#pragma unroll
    for (int mt = 0; mt < 4; mt++)
#pragma unroll
        for (int nt = 0; nt < 2; nt++)
#pragma unroll
            for (int e = 0; e < 4; e++) acc[mt][nt][e] = 0.f;

    const int a_row = (lane & 7) + ((lane >> 3) & 1) * 8;
    const int a_colb = (lane >> 4) * 8;
    const int b_row = lane & 7;
    const int b_colb = ((lane >> 3) & 1) * 8;
    const int ncol0 = wn * 32 + half * 16;

    const uint32_t aBases[3] = { sb + OFF_QH, sb + OFF_QL, sb + OFF_QH };
    const uint32_t bBases[3] = { sb + OFF_KH, sb + OFF_KH, sb + OFF_KL };

#pragma unroll
    for (int pass = 0; pass < 3; pass++) {
        const uint32_t aB = aBases[pass], bB = bBases[pass];
#pragma unroll
        for (int ks = 0; ks < 4; ks++) {
            uint32_t a[4][4], b[2][2];
#pragma unroll
            for (int mt = 0; mt < 4; mt++) {
                uint32_t addr = aB +
                    ((wm * 64 + mt * 16 + a_row) * TROW + ks * 16 + a_colb) * 2;
                ldsm_x4(addr, a[mt][0], a[mt][1], a[mt][2], a[mt][3]);
            }
#pragma unroll
            for (int nt = 0; nt < 2; nt++) {
                uint32_t addr = bB +
                    ((ncol0 + nt * 8 + b_row) * TROW + ks * 16 + b_colb) * 2;
                ldsm_x2(addr, b[nt][0], b[nt][1]);
            }
#pragma unroll
            for (int mt = 0; mt < 4; mt++)
#pragma unroll
                for (int nt = 0; nt < 2; nt++)
                    mma_bf16(acc[mt][nt], a[mt], b[nt]);
        }
    }
}

// triangular decode p -> (a, b), b <= a
__device__ __forceinline__ void tri_decode(int p, int& a, int& b) {
    a = (int)((sqrtf(8.0f * (float)p + 1.0f) - 1.0f) * 0.5f);
    while ((a + 1) * (a + 2) / 2 <= p) a++;
    while (a * (a + 1) / 2 > p) a--;
    b = p - a * (a + 1) / 2;
}

// ---------------------------------------------------------------------------
// Pass A: row sums only (no large stores). N-halved for register pressure.
// ---------------------------------------------------------------------------
__global__ __launch_bounds__(256, 2) void sums_kernel() {
    extern __shared__ char smem[];
    const uint32_t sb = smem_u32(smem);
    const int t = threadIdx.x, wid = t >> 5, lane = t & 31;

    int qt, kt;
    tri_decode(blockIdx.x, qt, kt);
    const bool diag = (kt == qt);
    const int bh = blockIdx.y;
    const int i0 = qt * 128, j0 = kt * 128;
    const size_t base = (size_t)bh * Sc;

    stage_tiles(smem, base, i0, j0, t);
    __syncthreads();

    const int wm = wid >> 2, wn = wid & 3;
    const int qrow = lane >> 2;
    const int cpair = (lane & 3) * 2;

    float rs0[4], rs1[4];
#pragma unroll
    for (int mt = 0; mt < 4; mt++) { rs0[mt] = 0.f; rs1[mt] = 0.f; }

#pragma unroll
    for (int half = 0; half < 2; half++) {
        float acc[4][2][4];
        compute_half(sb, wm, wn, half, lane, acc);
#pragma unroll
        for (int mt = 0; mt < 4; mt++) {
            const int r0l = wm * 64 + mt * 16 + qrow;
            const int r1l = r0l + 8;
#pragma unroll
            for (int nt = 0; nt < 2; nt++) {
                const int c = wn * 32 + half * 16 + nt * 8 + cpair;
                float* d = acc[mt][nt];
                if (!diag || c <= r0l)     rs0[mt] += ex2f(d[0]);
                if (!diag || c + 1 <= r0l) rs0[mt] += ex2f(d[1]);
                if (!diag || c <= r1l)     rs1[mt] += ex2f(d[2]);
                if (!diag || c + 1 <= r1l) rs1[mt] += ex2f(d[3]);
            }
        }
    }

#pragma unroll
    for (int mt = 0; mt < 4; mt++) {
        const int r0l = wm * 64 + mt * 16 + qrow;
        float s0 = rs0[mt], s1 = rs1[mt];
        s0 += __shfl_xor_sync(0xffffffffu, s0, 1);
        s0 += __shfl_xor_sync(0xffffffffu, s0, 2);
        s1 += __shfl_xor_sync(0xffffffffu, s1, 1);
        s1 += __shfl_xor_sync(0xffffffffu, s1, 2);
        if ((lane & 3) == 0) {
            atomicAdd(&g_rowsum[base + i0 + r0l], s0);
            atomicAdd(&g_rowsum[base + i0 + r0l + 8], s1);
        }
    }
}

// ---------------------------------------------------------------------------
// zfin: invZ per row + write the sink column of out.
// ---------------------------------------------------------------------------
__global__ __launch_bounds__(256) void zfin_kernel(const float* __restrict__ sinks,
                                                   float* __restrict__ out) {
    int row = blockIdx.x * blockDim.x + threadIdx.x;
    if (row >= NROWS) return;
    const int i = row & (Sc - 1);
    const float es = __expf(sinks[row]);
    const float invZ = 1.0f / (g_rowsum[row] + (float)(Sc - 1 - i) + es);
    g_invz[row] = invZ;
    out[(size_t)row * SP1 + Sc] = es * invZ;
}

// ---------------------------------------------------------------------------
// Fill kernel: strictly-masked tiles (kt > qt), out = invZ. Warp-per-row,
// STG.128 with alignment peeling (row starts are arbitrary mod 4: SP1 odd).
// ---------------------------------------------------------------------------
__global__ __launch_bounds__(256) void fill_kernel(float* __restrict__ out) {
    int a, b;
    tri_decode(blockIdx.x, a, b);     // a in [0,15), b <= a
    const int kt = a + 1;             // kt in [1,16)
    const int qt = b;                 // qt < kt
    const int bh = blockIdx.y;
    const int i0 = qt * 128, j0 = kt * 128;
    const size_t base = (size_t)bh * Sc;
    const int wid = threadIdx.x >> 5, lane = threadIdx.x & 31;

#pragma unroll
    for (int rr = 0; rr < 16; rr++) {
        const int r = wid * 16 + rr;
        const size_t rowg = base + i0 + r;
        const float invZ = g_invz[rowg];
        const size_t g0 = rowg * SP1 + j0;
        float* rp = out + g0;
        const int a0 = ((int)(4 - (g0 & 3))) & 3;     // scalar head count
        const int nvec = (128 - a0) >> 2;             // 31 or 32
        if (lane < a0) stcs(rp + lane, invZ);
        if (lane < nvec) stcs4(rp + a0 + 4 * lane, invZ);
        if (lane == 31 && a0) {
#pragma unroll
            for (int ti = 0; ti < 3; ti++)
                if (ti < 4 - a0) stcs(rp + a0 + 124 + ti, invZ);
        }
    }
}

// ---------------------------------------------------------------------------
// Pass B: causal tiles only. Recompute GEMM, write final e*invZ (diag tiles
// fill their upper part with invZ). N-halved.
// ---------------------------------------------------------------------------
__global__ __launch_bounds__(256, 2) void write_kernel(float* __restrict__ out) {
    extern __shared__ char smem[];
    const uint32_t sb = smem_u32(smem);
    const int t = threadIdx.x, wid = t >> 5, lane = t & 31;

    int qt, kt;
    tri_decode(blockIdx.x, qt, kt);
    const bool diag = (kt == qt);
    const int bh = blockIdx.y;
    const int i0 = qt * 128, j0 = kt * 128;
    const size_t base = (size_t)bh * Sc;

    stage_tiles(smem, base, i0, j0, t);
    __syncthreads();

    const int wm = wid >> 2, wn = wid & 3;
    const int qrow = lane >> 2;
    const int cpair = (lane & 3) * 2;

#pragma unroll
    for (int half = 0; half < 2; half++) {
        float acc[4][2][4];
        compute_half(sb, wm, wn, half, lane, acc);
#pragma unroll
        for (int mt = 0; mt < 4; mt++) {
            const int r0l = wm * 64 + mt * 16 + qrow;
            const int r1l = r0l + 8;
            const float iz0 = g_invz[base + i0 + r0l];
            const float iz1 = g_invz[base + i0 + r1l];
            float* orow0 = out + (base + (size_t)(i0 + r0l)) * SP1 + j0;
            float* orow1 = out + (base + (size_t)(i0 + r1l)) * SP1 + j0;
#pragma unroll
            for (int nt = 0; nt < 2; nt++) {
                const int c = wn * 32 + half * 16 + nt * 8 + cpair;
                float* d = acc[mt][nt];
                stcs(orow0 + c,     (!diag || c <= r0l)     ? ex2f(d[0]) * iz0 : iz0);
                stcs(orow0 + c + 1, (!diag || c + 1 <= r0l) ? ex2f(d[1]) * iz0 : iz0);
                stcs(orow1 + c,     (!diag || c <= r1l)     ? ex2f(d[2]) * iz1 : iz1);
                stcs(orow1 + c + 1, (!diag || c + 1 <= r1l) ? ex2f(d[3]) * iz1 : iz1);
            }
        }
    }
}

// ---------------------------------------------------------------------------
extern "C" void kernel_launch(void* const* d_in, const int* in_sizes, int n_in,
                              void* d_out, int out_size) {
    const float* q     = (const float*)d_in[0];
    const float* k     = (const float*)d_in[1];
    const float* sinks = (const float*)d_in[2];
    float* out = (float*)d_out;
    (void)in_sizes; (void)n_in; (void)out_size;

    cudaFuncSetAttribute(sums_kernel, cudaFuncAttributeMaxDynamicSharedMemorySize, SMEM_SZ);
    cudaFuncSetAttribute(write_kernel, cudaFuncAttributeMaxDynamicSharedMemorySize, SMEM_SZ);

    prep_kernel<<<NROWS / 256, 256>>>(k);
    prep2_kernel<<<NROWS * 16 / 256, 256>>>(q, k);
    sums_kernel<<<dim3(NT128, Bc * Hc), 256, SMEM_SZ>>>();
    zfin_kernel<<<NROWS / 256, 256>>>(sinks, out);
    fill_kernel<<<dim3(NFILL, Bc * Hc), 256>>>(out);
    write_kernel<<<dim3(NT128, Bc * Hc), 256, SMEM_SZ>>>(out);
}

// round 12
// speedup vs baseline: 2.5902x; 1.1541x over previous
#include <cuda_runtime.h>
#include <cuda_bf16.h>
#include <cstdint>

#define Bc 2
#define Hc 16
#define Sc 2048
#define Dc 64
#define NROWS (Bc * Hc * Sc)   // 65536
#define SP1 (Sc + 1)           // 2049
#define NT128 136              // 16*17/2 causal 128x128 tile pairs
#define NFILL 120              // 15*16/2 strictly-masked tile pairs

// Scratch
__device__ float g_invn[NROWS];    // log2e / ||k||
__device__ float g_rowsum[NROWS];  // sum of exps over lower triangle
__device__ float g_invz[NROWS];    // 1/Z
// Pre-split bf16 operands (hi/lo), K pre-scaled by log2e/||k||.
__device__ __nv_bfloat16 g_qh[NROWS * Dc];
__device__ __nv_bfloat16 g_ql[NROWS * Dc];
__device__ __nv_bfloat16 g_kh[NROWS * Dc];
__device__ __nv_bfloat16 g_kl[NROWS * Dc];

// ---------------------------------------------------------------------------
// helpers
// ---------------------------------------------------------------------------
__device__ __forceinline__ uint32_t smem_u32(const void* p) {
    uint32_t a;
    asm("{ .reg .u64 t; cvta.to.shared.u64 t, %1; cvt.u32.u64 %0, t; }" : "=r"(a) : "l"(p));
    return a;
}
__device__ __forceinline__ float ex2f(float x) {
    float r; asm("ex2.approx.f32 %0, %1;" : "=f"(r) : "f"(x)); return r;
}
__device__ __forceinline__ void stcs(float* p, float v) {
    asm volatile("st.global.cs.f32 [%0], %1;" :: "l"(p), "f"(v) : "memory");
}
__device__ __forceinline__ void stcs4(float* p, float v) {
    asm volatile("st.global.cs.v4.f32 [%0], {%1,%1,%1,%1};" :: "l"(p), "f"(v) : "memory");
}
__device__ __forceinline__ void ldsm_x4(uint32_t a, uint32_t& r0, uint32_t& r1,
                                        uint32_t& r2, uint32_t& r3) {
    asm volatile("ldmatrix.sync.aligned.m8n8.x4.shared.b16 {%0,%1,%2,%3}, [%4];"
                 : "=r"(r0), "=r"(r1), "=r"(r2), "=r"(r3) : "r"(a));
}
__device__ __forceinline__ void ldsm_x2(uint32_t a, uint32_t& r0, uint32_t& r1) {
    asm volatile("ldmatrix.sync.aligned.m8n8.x2.shared.b16 {%0,%1}, [%2];"
                 : "=r"(r0), "=r"(r1) : "r"(a));
}
__device__ __forceinline__ void mma_bf16(float* d, const uint32_t* a, const uint32_t* b) {
    asm volatile(
        "mma.sync.aligned.m16n8k16.row.col.f32.bf16.bf16.f32 "
        "{%0,%1,%2,%3}, {%4,%5,%6,%7}, {%8,%9}, {%0,%1,%2,%3};"
        : "+f"(d[0]), "+f"(d[1]), "+f"(d[2]), "+f"(d[3])
        : "r"(a[0]), "r"(a[1]), "r"(a[2]), "r"(a[3]), "r"(b[0]), "r"(b[1]));
}

// smem tiles: [128 rows][72 bf16] (144B padded rows -> ldmatrix conflict-free)
#define TROW 72
#define TBYTES (128 * TROW * 2)          // 18432
// write kernel: 4 tiles; sums kernel: 2 tiles (hi only)
#define OFF_QH 0
#define OFF_QL (1 * TBYTES)
#define OFF_KH (2 * TBYTES)
#define OFF_KL (3 * TBYTES)
#define SMEM_W (4 * TBYTES)              // 73728
#define SOFF_QH 0
#define SOFF_KH (1 * TBYTES)
#define SMEM_S (2 * TBYTES)              // 36864

// ---------------------------------------------------------------------------
// Kernel 1: per-key log2(e)/||k|| + zero row sums
// ---------------------------------------------------------------------------
__global__ __launch_bounds__(256) void prep_kernel(const float* __restrict__ k) {
    int row = blockIdx.x * blockDim.x + threadIdx.x;
    if (row >= NROWS) return;
    const float4* kr = (const float4*)(k + (size_t)row * Dc);
    float s = 0.f;
#pragma unroll
    for (int i = 0; i < Dc / 4; i++) {
        float4 v = kr[i];
        s += v.x * v.x + v.y * v.y + v.z * v.z + v.w * v.w;
    }
    g_invn[row] = 1.4426950408889634f * rsqrtf(s);
    g_rowsum[row] = 0.f;
}

// ---------------------------------------------------------------------------
// prep2: split Q and scaled-K into global bf16 hi/lo (once).
// ---------------------------------------------------------------------------
__global__ __launch_bounds__(256) void prep2_kernel(const float* __restrict__ q,
                                                    const float* __restrict__ k) {
    int rc = blockIdx.x * blockDim.x + threadIdx.x;   // 0 .. NROWS*16-1
    int row = rc >> 4, c4 = rc & 15;
    size_t eo = (size_t)row * Dc + c4 * 4;
    {
        float4 v = *(const float4*)(q + eo);
        union { __nv_bfloat16 b[4]; unsigned long long u; } H, L;
#pragma unroll
        for (int e = 0; e < 4; e++) {
            float x = (&v.x)[e];
            __nv_bfloat16 h = __float2bfloat16_rn(x);
            H.b[e] = h;
            L.b[e] = __float2bfloat16_rn(x - __bfloat162float(h));
        }
        *(unsigned long long*)(g_qh + eo) = H.u;
        *(unsigned long long*)(g_ql + eo) = L.u;
    }
    {
        float s = g_invn[row];
        float4 v = *(const float4*)(k + eo);
        union { __nv_bfloat16 b[4]; unsigned long long u; } H, L;
#pragma unroll
        for (int e = 0; e < 4; e++) {
            float x = (&v.x)[e] * s;
            __nv_bfloat16 h = __float2bfloat16_rn(x);
            H.b[e] = h;
            L.b[e] = __float2bfloat16_rn(x - __bfloat162float(h));
        }
        *(unsigned long long*)(g_kh + eo) = H.u;
        *(unsigned long long*)(g_kl + eo) = L.u;
    }
}

// ---------------------------------------------------------------------------
// staging helpers (16B copies from pre-split arrays)
// ---------------------------------------------------------------------------
__device__ __forceinline__ void stage2(char* smem, size_t base, int i0, int j0, int t) {
    const uint4* qh = (const uint4*)(g_qh + (base + i0) * Dc);
    const uint4* kh = (const uint4*)(g_kh + (base + j0) * Dc);
#pragma unroll
    for (int it = 0; it < 4; it++) {
        int idx = t + 256 * it;           // 0..1023
        int row = idx >> 3, ch = idx & 7;
        uint32_t so = (row * TROW + ch * 8) * 2;
        int gi = row * 8 + ch;
        *(uint4*)(smem + SOFF_QH + so) = qh[gi];
        *(uint4*)(smem + SOFF_KH + so) = kh[gi];
    }
}
__device__ __forceinline__ void stage4(char* smem, size_t base, int i0, int j0, int t) {
    const uint4* qh = (const uint4*)(g_qh + (base + i0) * Dc);
    const uint4* ql = (const uint4*)(g_ql + (base + i0) * Dc);
    const uint4* kh = (const uint4*)(g_kh + (base + j0) * Dc);
    const uint4* kl = (const uint4*)(g_kl + (base + j0) * Dc);
#pragma unroll
    for (int it = 0; it < 4; it++) {
        int idx = t + 256 * it;
        int row = idx >> 3, ch = idx & 7;
        uint32_t so = (row * TROW + ch * 8) * 2;
        int gi = row * 8 + ch;
        *(uint4*)(smem + OFF_QH + so) = qh[gi];
        *(uint4*)(smem + OFF_QL + so) = ql[gi];
        *(uint4*)(smem + OFF_KH + so) = kh[gi];
        *(uint4*)(smem + OFF_KL + so) = kl[gi];
    }
}

// One N-half GEMM, npass in {1,3}. acc[4][2][4] = 32 regs live.
template <int NPASS>
__device__ __forceinline__ void compute_half(uint32_t aHi, uint32_t aLo,
                                             uint32_t bHi, uint32_t bLo,
                                             int wm, int wn, int half,
                                             int lane, float acc[4][2][4]) {
#pragma unroll
    for (int mt = 0; mt < 4; mt++)
#pragma unroll
        for (int nt = 0; nt < 2; nt++)
#pragma unroll
            for (int e = 0; e < 4; e++) acc[mt][nt][e] = 0.f;

    const int a_row = (lane & 7) + ((lane >> 3) & 1) * 8;
    const int a_colb = (lane >> 4) * 8;
    const int b_row = lane & 7;
    const int b_colb = ((lane >> 3) & 1) * 8;
    const int ncol0 = wn * 32 + half * 16;

    const uint32_t aBases[3] = { aHi, aLo, aHi };
    const uint32_t bBases[3] = { bHi, bHi, bLo };

#pragma unroll
    for (int pass = 0; pass < NPASS; pass++) {
        const uint32_t aB = aBases[pass], bB = bBases[pass];
#pragma unroll
        for (int ks = 0; ks < 4; ks++) {
            uint32_t a[4][4], b[2][2];
#pragma unroll
            for (int mt = 0; mt < 4; mt++) {
                uint32_t addr = aB +
                    ((wm * 64 + mt * 16 + a_row) * TROW + ks * 16 + a_colb) * 2;
                ldsm_x4(addr, a[mt][0], a[mt][1], a[mt][2], a[mt][3]);
            }
#pragma unroll
            for (int nt = 0; nt < 2; nt++) {
                uint32_t addr = bB +
                    ((ncol0 + nt * 8 + b_row) * TROW + ks * 16 + b_colb) * 2;
                ldsm_x2(addr, b[nt][0], b[nt][1]);
            }
#pragma unroll
            for (int mt = 0; mt < 4; mt++)
#pragma unroll
                for (int nt = 0; nt < 2; nt++)
                    mma_bf16(acc[mt][nt], a[mt], b[nt]);
        }
    }
}

// triangular decode p -> (a, b), b <= a
__device__ __forceinline__ void tri_decode(int p, int& a, int& b) {
    a = (int)((sqrtf(8.0f * (float)p + 1.0f) - 1.0f) * 0.5f);
    while ((a + 1) * (a + 2) / 2 <= p) a++;
    while (a * (a + 1) / 2 > p) a--;
    b = p - a * (a + 1) / 2;
}

// ---------------------------------------------------------------------------
// Pass A: row sums, hi-only GEMM (Z tolerates ~1e-4 rel error; exact masked
// ones + 1/sqrt(n) averaging keep it there). 2 smem tiles, 3 CTAs/SM.
// ---------------------------------------------------------------------------
__global__ __launch_bounds__(256, 3) void sums_kernel() {
    extern __shared__ char smem[];
    const uint32_t sb = smem_u32(smem);
    const int t = threadIdx.x, wid = t >> 5, lane = t & 31;

    int qt, kt;
    tri_decode(blockIdx.x, qt, kt);
    const bool diag = (kt == qt);
    const int bh = blockIdx.y;
    const int i0 = qt * 128, j0 = kt * 128;
    const size_t base = (size_t)bh * Sc;

    stage2(smem, base, i0, j0, t);
    __syncthreads();

    const int wm = wid >> 2, wn = wid & 3;
    const int qrow = lane >> 2;
    const int cpair = (lane & 3) * 2;

    float rs0[4], rs1[4];
#pragma unroll
    for (int mt = 0; mt < 4; mt++) { rs0[mt] = 0.f; rs1[mt] = 0.f; }

#pragma unroll
    for (int half = 0; half < 2; half++) {
        float acc[4][2][4];
        compute_half<1>(sb + SOFF_QH, 0u, sb + SOFF_KH, 0u, wm, wn, half, lane, acc);
#pragma unroll
        for (int mt = 0; mt < 4; mt++) {
            const int r0l = wm * 64 + mt * 16 + qrow;
            const int r1l = r0l + 8;
#pragma unroll
            for (int nt = 0; nt < 2; nt++) {
                const int c = wn * 32 + half * 16 + nt * 8 + cpair;
                float* d = acc[mt][nt];
                if (!diag || c <= r0l)     rs0[mt] += ex2f(d[0]);
                if (!diag || c + 1 <= r0l) rs0[mt] += ex2f(d[1]);
                if (!diag || c <= r1l)     rs1[mt] += ex2f(d[2]);
                if (!diag || c + 1 <= r1l) rs1[mt] += ex2f(d[3]);
            }
        }
    }

#pragma unroll
    for (int mt = 0; mt < 4; mt++) {
        const int r0l = wm * 64 + mt * 16 + qrow;
        float s0 = rs0[mt], s1 = rs1[mt];
        s0 += __shfl_xor_sync(0xffffffffu, s0, 1);
        s0 += __shfl_xor_sync(0xffffffffu, s0, 2);
        s1 += __shfl_xor_sync(0xffffffffu, s1, 1);
        s1 += __shfl_xor_sync(0xffffffffu, s1, 2);
        if ((lane & 3) == 0) {
            atomicAdd(&g_rowsum[base + i0 + r0l], s0);
            atomicAdd(&g_rowsum[base + i0 + r0l + 8], s1);
        }
    }
}

// ---------------------------------------------------------------------------
// zfin: invZ per row + write the sink column of out.
// ---------------------------------------------------------------------------
__global__ __launch_bounds__(256) void zfin_kernel(const float* __restrict__ sinks,
                                                   float* __restrict__ out) {
    int row = blockIdx.x * blockDim.x + threadIdx.x;
    if (row >= NROWS) return;
    const int i = row & (Sc - 1);
    const float es = __expf(sinks[row]);
    const float invZ = 1.0f / (g_rowsum[row] + (float)(Sc - 1 - i) + es);
    g_invz[row] = invZ;
    out[(size_t)row * SP1 + Sc] = es * invZ;
}

// ---------------------------------------------------------------------------
// Fill kernel: strictly-masked tiles (kt > qt), out = invZ. Warp-per-row,
// STG.128 with alignment peeling.
// ---------------------------------------------------------------------------
__global__ __launch_bounds__(256) void fill_kernel(float* __restrict__ out) {
    int a, b;
    tri_decode(blockIdx.x, a, b);     // a in [0,15), b <= a
    const int kt = a + 1;
    const int qt = b;
    const int bh = blockIdx.y;
    const int i0 = qt * 128, j0 = kt * 128;
    const size_t base = (size_t)bh * Sc;
    const int wid = threadIdx.x >> 5, lane = threadIdx.x & 31;

#pragma unroll
    for (int rr = 0; rr < 16; rr++) {
        const int r = wid * 16 + rr;
        const size_t rowg = base + i0 + r;
        const float invZ = g_invz[rowg];
        const size_t g0 = rowg * SP1 + j0;
        float* rp = out + g0;
        const int a0 = ((int)(4 - (g0 & 3))) & 3;
        const int nvec = (128 - a0) >> 2;
        if (lane < a0) stcs(rp + lane, invZ);
        if (lane < nvec) stcs4(rp + a0 + 4 * lane, invZ);
        if (lane == 31 && a0) {
#pragma unroll
            for (int ti = 0; ti < 3; ti++)
                if (ti < 4 - a0) stcs(rp + a0 + 124 + ti, invZ);
        }
    }
}

// ---------------------------------------------------------------------------
// Pass B: causal tiles. Full 3-pass GEMM, write final e*invZ.
// ---------------------------------------------------------------------------
__global__ __launch_bounds__(256, 2) void write_kernel(float* __restrict__ out) {
    extern __shared__ char smem[];
    const uint32_t sb = smem_u32(smem);
    const int t = threadIdx.x, wid = t >> 5, lane = t & 31;

    int qt, kt;
    tri_decode(blockIdx.x, qt, kt);
    const bool diag = (kt == qt);
    const int bh = blockIdx.y;
    const int i0 = qt * 128, j0 = kt * 128;
    const size_t base = (size_t)bh * Sc;

    stage4(smem, base, i0, j0, t);
    __syncthreads();

    const int wm = wid >> 2, wn = wid & 3;
    const int qrow = lane >> 2;
    const int cpair = (lane & 3) * 2;

#pragma unroll
    for (int half = 0; half < 2; half++) {
        float acc[4][2][4];
        compute_half<3>(sb + OFF_QH, sb + OFF_QL, sb + OFF_KH, sb + OFF_KL,
                        wm, wn, half, lane, acc);
#pragma unroll
        for (int mt = 0; mt < 4; mt++) {
            const int r0l = wm * 64 + mt * 16 + qrow;
            const int r1l = r0l + 8;
            const float iz0 = g_invz[base + i0 + r0l];
            const float iz1 = g_invz[base + i0 + r1l];
            float* orow0 = out + (base + (size_t)(i0 + r0l)) * SP1 + j0;
            float* orow1 = out + (base + (size_t)(i0 + r1l)) * SP1 + j0;
#pragma unroll
            for (int nt = 0; nt < 2; nt++) {
                const int c = wn * 32 + half * 16 + nt * 8 + cpair;
                float* d = acc[mt][nt];
                stcs(orow0 + c,     (!diag || c <= r0l)     ? ex2f(d[0]) * iz0 : iz0);
                stcs(orow0 + c + 1, (!diag || c + 1 <= r0l) ? ex2f(d[1]) * iz0 : iz0);
                stcs(orow1 + c,     (!diag || c <= r1l)     ? ex2f(d[2]) * iz1 : iz1);
                stcs(orow1 + c + 1, (!diag || c + 1 <= r1l) ? ex2f(d[3]) * iz1 : iz1);
            }
        }
    }
}

// ---------------------------------------------------------------------------
extern "C" void kernel_launch(void* const* d_in, const int* in_sizes, int n_in,
                              void* d_out, int out_size) {
    const float* q     = (const float*)d_in[0];
    const float* k     = (const float*)d_in[1];
    const float* sinks = (const float*)d_in[2];
    float* out = (float*)d_out;
    (void)in_sizes; (void)n_in; (void)out_size;

    cudaFuncSetAttribute(sums_kernel, cudaFuncAttributeMaxDynamicSharedMemorySize, SMEM_S);
    cudaFuncSetAttribute(write_kernel, cudaFuncAttributeMaxDynamicSharedMemorySize, SMEM_W);

    prep_kernel<<<NROWS / 256, 256>>>(k);
    prep2_kernel<<<NROWS * 16 / 256, 256>>>(q, k);
    sums_kernel<<<dim3(NT128, Bc * Hc), 256, SMEM_S>>>();
    zfin_kernel<<<NROWS / 256, 256>>>(sinks, out);
    fill_kernel<<<dim3(NFILL, Bc * Hc), 256>>>(out);
    write_kernel<<<dim3(NT128, Bc * Hc), 256, SMEM_W>>>(out);
}